// round 1
// baseline (speedup 1.0000x reference)
#include <cuda_runtime.h>
#include <math.h>

#define L_ 2
#define F_ 128
#define O_ 128
#define N_ 1024
#define B_ 8
#define D_ 3

// ---------------- scratch (device globals: allocation-free) ----------------
__device__ float g_support[(size_t)D_ * B_ * N_ * O_];      // 12 MB
__device__ float g_agg    [(size_t)D_ * B_ * N_ * O_];      // 12 MB
__device__ float g_gi     [(size_t)D_ * B_ * N_ * 3 * O_];  // 36 MB
__device__ float g_gh     [(size_t)B_ * N_ * 3 * O_];       // 12 MB
__device__ float g_thw    [(size_t)N_ * B_ * O_];           // 4 MB
__device__ float g_x      [(size_t)N_ * B_ * O_];           // 4 MB
__device__ float g_wihT   [(size_t)L_ * O_ * 3 * O_];
__device__ float g_whhT   [(size_t)L_ * O_ * 3 * O_];

// ---------------- weight transpose: Wih/Whh [L,3O,O] -> [L,O,3O] -----------
__global__ void transpose_wts_kernel(const float* __restrict__ Wih,
                                     const float* __restrict__ Whh,
                                     float* __restrict__ WihT,
                                     float* __restrict__ WhhT) {
    int idx = blockIdx.x * blockDim.x + threadIdx.x;
    const int total = L_ * 3 * O_ * O_;
    if (idx >= total) return;
    int l = idx / (3 * O_ * O_);
    int r = idx % (3 * O_ * O_);
    int j = r / O_;   // 0..383 (row of Wih)
    int k = r % O_;   // 0..127
    int dst = l * O_ * 3 * O_ + k * 3 * O_ + j;
    WihT[dst] = Wih[idx];
    WhhT[dst] = Whh[idx];
}

// ---------------- generic batched SGEMM + bias ------------------------------
// C[batch][m][n] = sum_k A[m][k]*B[k][n] + bias[n]
// batch = d*BB + b; per-batch offsets via strides. All dims divide tiles.
// Tile: BM=BN=128, BK=8, 256 threads, 8x8 microtile.
__global__ __launch_bounds__(256, 2)
void gemm_bias_kernel(const float* __restrict__ A,
                      const float* __restrict__ Bm,
                      float* __restrict__ C,
                      const float* __restrict__ bias,
                      int M, int K, int Ncols,
                      int lda, int ldb,
                      long sAd, long sAb,
                      long sBd, long sBb,
                      long sCbatch, long sBiasD, int BB) {
    const int batch = blockIdx.z;
    const int d = batch / BB;
    const int b = batch % BB;
    A  += (long)d * sAd + (long)b * sAb;
    Bm += (long)d * sBd + (long)b * sBb;
    C  += (long)batch * sCbatch;

    __shared__ float As[8][128];
    __shared__ float Bs[8][128];

    const int tid = threadIdx.x;
    const int row0 = blockIdx.y * 128;
    const int col0 = blockIdx.x * 128;

    // A staging: 128x8 tile = 256 float4 (transposed into As[k][m])
    const int aRow = tid >> 1;           // 0..127
    const int aCol = (tid & 1) << 2;     // 0 or 4
    // B staging: 8x128 tile = 256 float4
    const int bRow = tid >> 5;           // 0..7
    const int bCol = (tid & 31) << 2;    // 0..124

    const int ty = tid >> 4;             // 0..15
    const int tx = tid & 15;             // 0..15

    float acc[8][8];
#pragma unroll
    for (int i = 0; i < 8; i++)
#pragma unroll
        for (int j = 0; j < 8; j++) acc[i][j] = 0.f;

    const float* Aptr = A + (long)(row0 + aRow) * lda + aCol;
    const float* Bptr = Bm + (long)bRow * ldb + col0 + bCol;

    for (int k0 = 0; k0 < K; k0 += 8) {
        float4 av = *(const float4*)(Aptr + k0);
        float4 bv = *(const float4*)(Bptr + (long)k0 * ldb);
        As[aCol + 0][aRow] = av.x;
        As[aCol + 1][aRow] = av.y;
        As[aCol + 2][aRow] = av.z;
        As[aCol + 3][aRow] = av.w;
        *(float4*)&Bs[bRow][bCol] = bv;
        __syncthreads();

#pragma unroll
        for (int k = 0; k < 8; k++) {
            float4 a0 = *(const float4*)&As[k][ty * 8];
            float4 a1 = *(const float4*)&As[k][ty * 8 + 4];
            float4 b0 = *(const float4*)&Bs[k][tx * 8];
            float4 b1 = *(const float4*)&Bs[k][tx * 8 + 4];
            float ar[8] = {a0.x, a0.y, a0.z, a0.w, a1.x, a1.y, a1.z, a1.w};
            float br[8] = {b0.x, b0.y, b0.z, b0.w, b1.x, b1.y, b1.z, b1.w};
#pragma unroll
            for (int i = 0; i < 8; i++)
#pragma unroll
                for (int j = 0; j < 8; j++)
                    acc[i][j] = fmaf(ar[i], br[j], acc[i][j]);
        }
        __syncthreads();
    }

    float bvals[8];
    if (bias) {
        const float* bp = bias + (long)d * sBiasD + col0 + tx * 8;
#pragma unroll
        for (int j = 0; j < 8; j++) bvals[j] = bp[j];
    } else {
#pragma unroll
        for (int j = 0; j < 8; j++) bvals[j] = 0.f;
    }

#pragma unroll
    for (int i = 0; i < 8; i++) {
        long row = row0 + ty * 8 + i;
        float* cp = C + row * (long)Ncols + col0 + tx * 8;
        float4 o0, o1;
        o0.x = acc[i][0] + bvals[0]; o0.y = acc[i][1] + bvals[1];
        o0.z = acc[i][2] + bvals[2]; o0.w = acc[i][3] + bvals[3];
        o1.x = acc[i][4] + bvals[4]; o1.y = acc[i][5] + bvals[5];
        o1.z = acc[i][6] + bvals[6]; o1.w = acc[i][7] + bvals[7];
        *(float4*)(cp)     = o0;
        *(float4*)(cp + 4) = o1;
    }
}

// ---------------- fused GRU + d-sum + relu + highway -----------------------
__device__ __forceinline__ float sigm(float x) { return 1.f / (1.f + expf(-x)); }

__global__ void gru_combine_kernel(const float* __restrict__ gi,
                                   const float* __restrict__ gh,
                                   const float* __restrict__ xsrc,
                                   const float* __restrict__ thw,
                                   float* __restrict__ xdst) {
    int idx = blockIdx.x * blockDim.x + threadIdx.x;  // over N*B*O
    if (idx >= N_ * B_ * O_) return;
    const int o = idx & (O_ - 1);
    const int nb = idx / O_;         // n*B + b
    const int b = nb & (B_ - 1);
    const int n = nb / B_;

    const float h = xsrc[idx];
    const long ghbase = ((long)b * N_ + n) * (3 * O_);
    const float ghr = gh[ghbase + o];
    const float ghz = gh[ghbase + O_ + o];
    const float ghn = gh[ghbase + 2 * O_ + o];

    float acc = 0.f;
#pragma unroll
    for (int d = 0; d < D_; d++) {
        const long gbase = (((long)d * B_ + b) * N_ + n) * (3 * O_);
        const float gir = gi[gbase + o];
        const float giz = gi[gbase + O_ + o];
        const float gin = gi[gbase + 2 * O_ + o];
        const float r = sigm(gir + ghr);
        const float z = sigm(giz + ghz);
        const float nn = tanhf(gin + r * ghn);
        acc += (1.f - z) * nn + z * h;
    }
    const float out = fmaxf(acc, 0.f);
    const float t = fmaxf(thw[idx], 0.f);
    xdst[idx] = out * t + h * (1.f - t);
}

// ---------------- launch ----------------------------------------------------
extern "C" void kernel_launch(void* const* d_in, const int* in_sizes, int n_in,
                              void* d_out, int out_size) {
    const float* inputs = (const float*)d_in[0];  // [N,B,F]
    const float* adj    = (const float*)d_in[1];  // [D,B,N,N]
    const float* W      = (const float*)d_in[2];  // [L,D,F,O]
    const float* Bc     = (const float*)d_in[3];  // [L,D,O]
    const float* Wh     = (const float*)d_in[4];  // [L,F,O]
    const float* Bh     = (const float*)d_in[5];  // [L,O]
    const float* Wih    = (const float*)d_in[6];  // [L,3O,O]
    const float* Whh    = (const float*)d_in[7];  // [L,3O,O]
    const float* bih    = (const float*)d_in[8];  // [L,3O]
    const float* bhh    = (const float*)d_in[9];  // [L,3O]
    float* out = (float*)d_out;

    float *support, *agg, *gi, *gh, *thw, *xbuf, *wihT, *whhT;
    cudaGetSymbolAddress((void**)&support, g_support);
    cudaGetSymbolAddress((void**)&agg,     g_agg);
    cudaGetSymbolAddress((void**)&gi,      g_gi);
    cudaGetSymbolAddress((void**)&gh,      g_gh);
    cudaGetSymbolAddress((void**)&thw,     g_thw);
    cudaGetSymbolAddress((void**)&xbuf,    g_x);
    cudaGetSymbolAddress((void**)&wihT,    g_wihT);
    cudaGetSymbolAddress((void**)&whhT,    g_whhT);

    {
        const int total = L_ * 3 * O_ * O_;
        transpose_wts_kernel<<<(total + 255) / 256, 256>>>(Wih, Whh, wihT, whhT);
    }

    for (int l = 0; l < L_; l++) {
        const float* xs = (l == 0) ? inputs : xbuf;
        float* xd = (l == L_ - 1) ? out : xbuf;

        // support[d,b,n,o] = x[n,b,:] @ W[l,d]  + Bc[l,d]
        gemm_bias_kernel<<<dim3(1, N_ / 128, D_ * B_), 256>>>(
            xs, W + (long)l * D_ * F_ * O_, support, Bc + (long)l * D_ * O_,
            N_, F_, O_, B_ * F_, O_,
            /*sAd*/0, /*sAb*/F_, /*sBd*/(long)F_ * O_, /*sBb*/0,
            /*sC*/(long)N_ * O_, /*sBias*/O_, B_);

        // agg[d,b,m,o] = adj[d,b] @ support[d,b]
        gemm_bias_kernel<<<dim3(1, N_ / 128, D_ * B_), 256>>>(
            adj, support, agg, nullptr,
            N_, N_, O_, N_, O_,
            (long)B_ * N_ * N_, (long)N_ * N_,
            (long)B_ * N_ * O_, (long)N_ * O_,
            (long)N_ * O_, 0, B_);

        // gh[b,n,:] = x[n,b,:] @ WhhT[l] + bhh[l]
        gemm_bias_kernel<<<dim3(3, N_ / 128, B_), 256>>>(
            xs, whhT + (long)l * O_ * 3 * O_, gh, bhh + (long)l * 3 * O_,
            N_, O_, 3 * O_, B_ * F_, 3 * O_,
            0, F_, 0, 0,
            (long)N_ * 3 * O_, 0, B_);

        // gi[d,b,n,:] = agg[d,b,n,:] @ WihT[l] + bih[l]
        gemm_bias_kernel<<<dim3(3, N_ / 128, D_ * B_), 256>>>(
            agg, wihT + (long)l * O_ * 3 * O_, gi, bih + (long)l * 3 * O_,
            N_, O_, 3 * O_, O_, 3 * O_,
            (long)B_ * N_ * O_, (long)N_ * O_, 0, 0,
            (long)N_ * 3 * O_, 0, B_);

        // thw[n,b,o] = x[n,b,:] @ Wh[l] + Bh[l]   (relu applied in combine)
        gemm_bias_kernel<<<dim3(1, (N_ * B_) / 128, 1), 256>>>(
            xs, Wh + (long)l * F_ * O_, thw, Bh + (long)l * O_,
            N_ * B_, F_, O_, F_, O_,
            0, 0, 0, 0,
            0, 0, 1);

        gru_combine_kernel<<<(N_ * B_ * O_) / 256, 256>>>(gi, gh, xs, thw, xd);
    }
}

// round 4
// speedup vs baseline: 1.7840x; 1.7840x over previous
#include <cuda_runtime.h>
#include <cuda_bf16.h>
#include <math.h>
#include <stdint.h>

#define L_ 2
#define F_ 128
#define O_ 128
#define N_ 1024
#define B_ 8
#define D_ 3

// ---------------- scratch (device globals, POD only) ------------------------
__device__ unsigned short g_adj2 [(size_t)D_ * B_ * N_ * 2 * N_];   // 96 MB
__device__ unsigned short g_x2   [(size_t)B_ * N_ * 2 * F_];
__device__ unsigned short g_sup2 [(size_t)D_ * B_ * 2 * N_ * O_];
__device__ unsigned short g_agg2 [(size_t)D_ * B_ * N_ * 2 * O_];
__device__ unsigned short g_W2   [(size_t)L_ * D_ * 2 * F_ * O_];
__device__ unsigned short g_whhT2[(size_t)L_ * 2 * O_ * 3 * O_];
__device__ unsigned short g_wihT2[(size_t)L_ * 2 * O_ * 3 * O_];
__device__ unsigned short g_wh2  [(size_t)L_ * 2 * F_ * O_];
__device__ float g_support[(size_t)D_ * B_ * N_ * O_];
__device__ float g_agg    [(size_t)D_ * B_ * N_ * O_];
__device__ float g_gi     [(size_t)D_ * B_ * N_ * 3 * O_];
__device__ float g_gh     [(size_t)B_ * N_ * 3 * O_];
__device__ float g_thw    [(size_t)B_ * N_ * O_];
__device__ float g_x      [(size_t)N_ * B_ * O_];
__device__ float g_whhT   [(size_t)L_ * O_ * 3 * O_];
__device__ float g_wihT   [(size_t)L_ * O_ * 3 * O_];

// ---------------- weight transpose: Wih/Whh [L,3O,O] -> [L,O,3O] -----------
__global__ void transpose_wts_kernel(const float* __restrict__ Wih,
                                     const float* __restrict__ Whh,
                                     float* __restrict__ WihT,
                                     float* __restrict__ WhhT) {
    int idx = blockIdx.x * blockDim.x + threadIdx.x;
    const int total = L_ * 3 * O_ * O_;
    if (idx >= total) return;
    int l = idx / (3 * O_ * O_);
    int r = idx % (3 * O_ * O_);
    int j = r / O_;
    int k = r % O_;
    int dst = l * O_ * 3 * O_ + k * 3 * O_ + j;
    WihT[dst] = Wih[idx];
    WhhT[dst] = Whh[idx];
}

// ---------------- hi/lo split packing ---------------------------------------
__device__ __forceinline__ void split_pack8(const float* v, uint32_t* ph, uint32_t* pl) {
#pragma unroll
    for (int i = 0; i < 4; i++) {
        float a = v[2 * i], b = v[2 * i + 1];
        __nv_bfloat162 h2 = __floats2bfloat162_rn(a, b);
        ph[i] = *reinterpret_cast<const uint32_t*>(&h2);
        float ra = a - __low2float(h2);
        float rb = b - __high2float(h2);
        __nv_bfloat162 l2 = __floats2bfloat162_rn(ra, rb);
        pl[i] = *reinterpret_cast<const uint32_t*>(&l2);
    }
}

// splitA: fp32 (strided) [z][M][K] -> bf16 out[z][M][2K] = [hi | lo]
__global__ void splitA_kernel(const float* __restrict__ in,
                              unsigned short* __restrict__ out,
                              long inBatch, long inRow, int M, int K) {
    long idx = (long)blockIdx.x * blockDim.x + threadIdx.x;
    long total = (long)M * (K / 8);
    if (idx >= total) return;
    int m = (int)(idx / (K / 8));
    int kc = (int)(idx % (K / 8)) * 8;
    const float* src = in + (long)blockIdx.z * inBatch + (long)m * inRow + kc;
    float4 v0 = *(const float4*)(src);
    float4 v1 = *(const float4*)(src + 4);
    float v[8] = {v0.x, v0.y, v0.z, v0.w, v1.x, v1.y, v1.z, v1.w};
    uint32_t ph[4], pl[4];
    split_pack8(v, ph, pl);
    unsigned short* dst = out + (long)blockIdx.z * M * 2 * K + (long)m * 2 * K + kc;
    *(uint4*)(dst)     = make_uint4(ph[0], ph[1], ph[2], ph[3]);
    *(uint4*)(dst + K) = make_uint4(pl[0], pl[1], pl[2], pl[3]);
}

// splitB: fp32 contiguous [z][K][N] -> bf16 out[z][2K][N] = [hi ; lo]
__global__ void splitB_kernel(const float* __restrict__ in,
                              unsigned short* __restrict__ out,
                              int K, int Ncols) {
    long idx = (long)blockIdx.x * blockDim.x + threadIdx.x;
    long total = (long)K * (Ncols / 8);
    if (idx >= total) return;
    int k = (int)(idx / (Ncols / 8));
    int nc = (int)(idx % (Ncols / 8)) * 8;
    const float* src = in + (long)blockIdx.z * K * Ncols + (long)k * Ncols + nc;
    float4 v0 = *(const float4*)(src);
    float4 v1 = *(const float4*)(src + 4);
    float v[8] = {v0.x, v0.y, v0.z, v0.w, v1.x, v1.y, v1.z, v1.w};
    uint32_t ph[4], pl[4];
    split_pack8(v, ph, pl);
    unsigned short* dst = out + (long)blockIdx.z * 2 * K * Ncols + (long)k * Ncols + nc;
    *(uint4*)(dst)                   = make_uint4(ph[0], ph[1], ph[2], ph[3]);
    *(uint4*)(dst + (long)K * Ncols) = make_uint4(pl[0], pl[1], pl[2], pl[3]);
}

// ---------------- bf16 tensor-core GEMM (3-term compensated) ----------------
__device__ __forceinline__ void ldsm_x4(uint32_t* r, uint32_t addr) {
    asm volatile("ldmatrix.sync.aligned.m8n8.x4.shared.b16 {%0,%1,%2,%3}, [%4];"
                 : "=r"(r[0]), "=r"(r[1]), "=r"(r[2]), "=r"(r[3]) : "r"(addr));
}
__device__ __forceinline__ void ldsm_x2t(uint32_t* r, uint32_t addr) {
    asm volatile("ldmatrix.sync.aligned.m8n8.x2.trans.shared.b16 {%0,%1}, [%2];"
                 : "=r"(r[0]), "=r"(r[1]) : "r"(addr));
}
__device__ __forceinline__ void mma_bf16(float* d, const uint32_t* a, const uint32_t* b) {
    asm volatile("mma.sync.aligned.m16n8k16.row.col.f32.bf16.bf16.f32 "
                 "{%0,%1,%2,%3}, {%4,%5,%6,%7}, {%8,%9}, {%0,%1,%2,%3};"
                 : "+f"(d[0]), "+f"(d[1]), "+f"(d[2]), "+f"(d[3])
                 : "r"(a[0]), "r"(a[1]), "r"(a[2]), "r"(a[3]), "r"(b[0]), "r"(b[1]));
}

__device__ __forceinline__ void load_tile(
    const unsigned short* Ag0, const unsigned short* Ag1,
    const unsigned short* Bg0, const unsigned short* Bg1,
    int k3, int twoK, int K, int Ncols,
    uint4& va0, uint4& va1, uint4& vb0, uint4& vb1) {
    int aOff = k3 - (k3 >= twoK ? twoK : 0);
    int bOff = k3 - (k3 >= K ? K : 0);
    va0 = *(const uint4*)(Ag0 + aOff);
    va1 = *(const uint4*)(Ag1 + aOff);
    vb0 = *(const uint4*)(Bg0 + (long)bOff * Ncols);
    vb1 = *(const uint4*)(Bg1 + (long)bOff * Ncols);
}

// C[z][m][n] = sum_{k3<3K} A2[m][aOff(k3)] * B2[bOff(k3)][n] (+ bias[n])
// A2: [M][2K]=[Ah|Al], B2: [2K][N]=[Bh;Bl]; terms Ah*Bh, Al*Bh, Ah*Bl.
// Tile 128x128x32, 8 warps (2x4), warp 64x32.
__global__ __launch_bounds__(256)
void gemm_bf16_kernel(const unsigned short* __restrict__ A2,
                      const unsigned short* __restrict__ B2,
                      float* __restrict__ C, const float* __restrict__ bias,
                      int M, int K, int Ncols,
                      long sAd, long sAb, long sBd, long sBb,
                      long sCb, long sBiasD, int BB) {
    const int z = blockIdx.z;
    const int d = z / BB;
    const int b = z % BB;
    A2 += (long)d * sAd + (long)b * sAb;
    B2 += (long)d * sBd + (long)b * sBb;
    C  += (long)z * sCb;

    const int twoK = 2 * K;
    const int row0 = blockIdx.y * 128;
    const int col0 = blockIdx.x * 128;

    __shared__ uint4 As4[2][512];
    __shared__ uint4 Bs4[2][512];

    const int tid  = threadIdx.x;
    const int lane = tid & 31;
    const int warp = tid >> 5;
    const int wm = warp >> 2;
    const int wn = warp & 3;

    const int arow0 = tid >> 2, ac = tid & 3;
    const int brow0 = tid >> 4, bc = tid & 15;

    const unsigned short* Ag0 = A2 + (long)(row0 + arow0) * twoK + ac * 8;
    const unsigned short* Ag1 = A2 + (long)(row0 + arow0 + 64) * twoK + ac * 8;
    const unsigned short* Bg0 = B2 + (long)brow0 * Ncols + col0 + bc * 8;
    const unsigned short* Bg1 = B2 + (long)(brow0 + 16) * Ncols + col0 + bc * 8;

    const int asIdx0 = arow0 * 4 + (ac ^ ((arow0 >> 1) & 3));
    const int asIdx1 = asIdx0 + 256;
    const int bsIdx0 = brow0 * 16 + (bc ^ (brow0 & 7));
    const int bsIdx1 = bsIdx0 + 256;

    const uint32_t asB = (uint32_t)__cvta_generic_to_shared(&As4[0][0]);
    const uint32_t bsB = (uint32_t)__cvta_generic_to_shared(&Bs4[0][0]);

    uint32_t aAddr[2][4], bAddr[2][4];
#pragma unroll
    for (int ks = 0; ks < 2; ks++) {
#pragma unroll
        for (int mi = 0; mi < 4; mi++) {
            int r = wm * 64 + mi * 16 + (lane & 15);
            int c = ks * 2 + (lane >> 4);
            aAddr[ks][mi] = asB + (uint32_t)(r * 4 + (c ^ ((r >> 1) & 3))) * 16u;
        }
#pragma unroll
        for (int ni = 0; ni < 4; ni++) {
            int r = ks * 16 + (lane & 15);
            int c = wn * 4 + ni;
            bAddr[ks][ni] = bsB + (uint32_t)(r * 16 + (c ^ (r & 7))) * 16u;
        }
    }

    float acc[4][4][4];
#pragma unroll
    for (int mi = 0; mi < 4; mi++)
#pragma unroll
        for (int ni = 0; ni < 4; ni++)
#pragma unroll
            for (int q = 0; q < 4; q++) acc[mi][ni][q] = 0.f;

    {
        uint4 va0, va1, vb0, vb1;
        load_tile(Ag0, Ag1, Bg0, Bg1, 0, twoK, K, Ncols, va0, va1, vb0, vb1);
        As4[0][asIdx0] = va0; As4[0][asIdx1] = va1;
        Bs4[0][bsIdx0] = vb0; Bs4[0][bsIdx1] = vb1;
    }
    __syncthreads();

    const int nT = (3 * K) >> 5;
    for (int kt = 0; kt < nT; kt++) {
        const int buf = kt & 1;
        const uint32_t bofs = (uint32_t)buf * 8192u;
        uint4 na0, na1, nb0, nb1;
        const bool more = (kt + 1 < nT);
        if (more)
            load_tile(Ag0, Ag1, Bg0, Bg1, (kt + 1) << 5, twoK, K, Ncols, na0, na1, nb0, nb1);

#pragma unroll
        for (int ks = 0; ks < 2; ks++) {
            uint32_t afr[4][4], bfr[4][2];
#pragma unroll
            for (int mi = 0; mi < 4; mi++) ldsm_x4(afr[mi], aAddr[ks][mi] + bofs);
#pragma unroll
            for (int ni = 0; ni < 4; ni++) ldsm_x2t(bfr[ni], bAddr[ks][ni] + bofs);
#pragma unroll
            for (int mi = 0; mi < 4; mi++)
#pragma unroll
                for (int ni = 0; ni < 4; ni++)
                    mma_bf16(acc[mi][ni], afr[mi], bfr[ni]);
        }

        if (more) {
            const int nbuf = buf ^ 1;
            As4[nbuf][asIdx0] = na0; As4[nbuf][asIdx1] = na1;
            Bs4[nbuf][bsIdx0] = nb0; Bs4[nbuf][bsIdx1] = nb1;
        }
        __syncthreads();
    }

    const float* bp = bias ? (bias + (long)d * sBiasD) : (const float*)0;
#pragma unroll
    for (int mi = 0; mi < 4; mi++) {
        const int r0 = row0 + wm * 64 + mi * 16 + (lane >> 2);
#pragma unroll
        for (int ni = 0; ni < 4; ni++) {
            const int cc = col0 + wn * 32 + ni * 8 + (lane & 3) * 2;
            float bx = 0.f, by = 0.f;
            if (bp) { bx = bp[cc]; by = bp[cc + 1]; }
            float* p0 = C + (long)r0 * Ncols + cc;
            float* p1 = p0 + 8L * Ncols;
            p0[0] = acc[mi][ni][0] + bx;
            p0[1] = acc[mi][ni][1] + by;
            p1[0] = acc[mi][ni][2] + bx;
            p1[1] = acc[mi][ni][3] + by;
        }
    }
}

// ---------------- fused GRU + d-sum + relu + highway -----------------------
__device__ __forceinline__ float sigm(float x) { return 1.f / (1.f + expf(-x)); }

__global__ void gru_combine_kernel(const float* __restrict__ gi,
                                   const float* __restrict__ gh,
                                   const float* __restrict__ xsrc,
                                   const float* __restrict__ thw,
                                   float* __restrict__ xdst) {
    int idx = blockIdx.x * blockDim.x + threadIdx.x;  // (n,b,o)
    if (idx >= N_ * B_ * O_) return;
    const int o = idx & (O_ - 1);
    const int nb = idx / O_;
    const int b = nb & (B_ - 1);
    const int n = nb / B_;

    const float h = xsrc[idx];
    const long ghbase = ((long)b * N_ + n) * (3 * O_);
    const float ghr = gh[ghbase + o];
    const float ghz = gh[ghbase + O_ + o];
    const float ghn = gh[ghbase + 2 * O_ + o];

    float acc = 0.f;
#pragma unroll
    for (int d = 0; d < D_; d++) {
        const long gbase = (((long)d * B_ + b) * N_ + n) * (3 * O_);
        const float gir = gi[gbase + o];
        const float giz = gi[gbase + O_ + o];
        const float gin = gi[gbase + 2 * O_ + o];
        const float r = sigm(gir + ghr);
        const float zz = sigm(giz + ghz);
        const float nn = tanhf(gin + r * ghn);
        acc += (1.f - zz) * nn + zz * h;
    }
    const float outv = fmaxf(acc, 0.f);
    const float t = fmaxf(thw[((long)b * N_ + n) * O_ + o], 0.f);
    xdst[idx] = outv * t + h * (1.f - t);
}

// ---------------- launch ----------------------------------------------------
extern "C" void kernel_launch(void* const* d_in, const int* in_sizes, int n_in,
                              void* d_out, int out_size) {
    const float* inputs = (const float*)d_in[0];
    const float* adj    = (const float*)d_in[1];
    const float* W      = (const float*)d_in[2];
    const float* Bc     = (const float*)d_in[3];
    const float* Wh     = (const float*)d_in[4];
    const float* Bh     = (const float*)d_in[5];
    const float* Wih    = (const float*)d_in[6];
    const float* Whh    = (const float*)d_in[7];
    const float* bih    = (const float*)d_in[8];
    const float* bhh    = (const float*)d_in[9];
    float* out = (float*)d_out;

    unsigned short *adj2, *x2, *sup2, *agg2, *W2, *whhT2, *wihT2, *wh2;
    float *support, *agg, *gi, *gh, *thw, *xbuf, *whhT, *wihT;
    cudaGetSymbolAddress((void**)&adj2,  g_adj2);
    cudaGetSymbolAddress((void**)&x2,    g_x2);
    cudaGetSymbolAddress((void**)&sup2,  g_sup2);
    cudaGetSymbolAddress((void**)&agg2,  g_agg2);
    cudaGetSymbolAddress((void**)&W2,    g_W2);
    cudaGetSymbolAddress((void**)&whhT2, g_whhT2);
    cudaGetSymbolAddress((void**)&wihT2, g_wihT2);
    cudaGetSymbolAddress((void**)&wh2,   g_wh2);
    cudaGetSymbolAddress((void**)&support, g_support);
    cudaGetSymbolAddress((void**)&agg,     g_agg);
    cudaGetSymbolAddress((void**)&gi,      g_gi);
    cudaGetSymbolAddress((void**)&gh,      g_gh);
    cudaGetSymbolAddress((void**)&thw,     g_thw);
    cudaGetSymbolAddress((void**)&xbuf,    g_x);
    cudaGetSymbolAddress((void**)&whhT,    g_whhT);
    cudaGetSymbolAddress((void**)&wihT,    g_wihT);

    // ---- one-time conversions ----
    transpose_wts_kernel<<<(L_ * 3 * O_ * O_ + 255) / 256, 256>>>(Wih, Whh, wihT, whhT);
    splitB_kernel<<<dim3((F_ * O_ / 8 + 255) / 256, 1, L_ * D_), 256>>>(W, W2, F_, O_);
    splitB_kernel<<<dim3((O_ * 3 * O_ / 8 + 255) / 256, 1, L_), 256>>>(whhT, whhT2, O_, 3 * O_);
    splitB_kernel<<<dim3((O_ * 3 * O_ / 8 + 255) / 256, 1, L_), 256>>>(wihT, wihT2, O_, 3 * O_);
    splitB_kernel<<<dim3((F_ * O_ / 8 + 255) / 256, 1, L_), 256>>>(Wh, wh2, F_, O_);
    splitA_kernel<<<dim3((N_ * N_ / 8 + 255) / 256, 1, D_ * B_), 256>>>(
        adj, adj2, (long)N_ * N_, (long)N_, N_, N_);

    for (int l = 0; l < L_; l++) {
        const float* xs = (l == 0) ? inputs : xbuf;
        float* xd = (l == L_ - 1) ? out : xbuf;

        // x2[b][n][2F] from xs [N,B,F]
        splitA_kernel<<<dim3((N_ * F_ / 8 + 255) / 256, 1, B_), 256>>>(
            xs, x2, (long)F_, (long)B_ * F_, N_, F_);

        // support[d,b] = x2[b] @ W2[l,d] + Bc[l,d]
        gemm_bf16_kernel<<<dim3(1, N_ / 128, D_ * B_), 256>>>(
            x2, W2 + (long)l * D_ * 2 * F_ * O_, support, Bc + (long)l * D_ * O_,
            N_, F_, O_,
            0, (long)N_ * 2 * F_, (long)2 * F_ * O_, 0,
            (long)N_ * O_, O_, B_);

        // sup2[z][2N][O]
        splitB_kernel<<<dim3((N_ * O_ / 8 + 255) / 256, 1, D_ * B_), 256>>>(
            support, sup2, N_, O_);

        // agg[d,b] = adj2[d,b] @ sup2[d,b]
        gemm_bf16_kernel<<<dim3(1, N_ / 128, D_ * B_), 256>>>(
            adj2, sup2, agg, (const float*)0,
            N_, N_, O_,
            (long)B_ * N_ * 2 * N_, (long)N_ * 2 * N_,
            (long)B_ * 2 * N_ * O_, (long)2 * N_ * O_,
            (long)N_ * O_, 0, B_);

        // agg2[z][N][2O]
        splitA_kernel<<<dim3((N_ * O_ / 8 + 255) / 256, 1, D_ * B_), 256>>>(
            agg, agg2, (long)N_ * O_, (long)O_, N_, O_);

        // gh[b] = x2[b] @ whhT2[l] + bhh[l]
        gemm_bf16_kernel<<<dim3(3, N_ / 128, B_), 256>>>(
            x2, whhT2 + (long)l * 2 * O_ * 3 * O_, gh, bhh + (long)l * 3 * O_,
            N_, O_, 3 * O_,
            0, (long)N_ * 2 * F_, 0, 0,
            (long)N_ * 3 * O_, 0, B_);

        // gi[d,b] = agg2[d,b] @ wihT2[l] + bih[l]
        gemm_bf16_kernel<<<dim3(3, N_ / 128, D_ * B_), 256>>>(
            agg2, wihT2 + (long)l * 2 * O_ * 3 * O_, gi, bih + (long)l * 3 * O_,
            N_, O_, 3 * O_,
            (long)B_ * N_ * 2 * O_, (long)N_ * 2 * O_, 0, 0,
            (long)N_ * 3 * O_, 0, B_);

        // thw[b] = x2[b] @ wh2[l] + Bh[l]
        gemm_bf16_kernel<<<dim3(1, N_ / 128, B_), 256>>>(
            x2, wh2 + (long)l * 2 * F_ * O_, thw, Bh + (long)l * O_,
            N_, F_, O_,
            0, (long)N_ * 2 * F_, 0, 0,
            (long)N_ * O_, 0, B_);

        gru_combine_kernel<<<(N_ * B_ * O_) / 256, 256>>>(gi, gh, xs, thw, xd);
    }
}

// round 5
// speedup vs baseline: 2.1741x; 1.2187x over previous
#include <cuda_runtime.h>
#include <cuda_bf16.h>
#include <math.h>
#include <stdint.h>

#define L_ 2
#define F_ 128
#define O_ 128
#define N_ 1024
#define B_ 8
#define D_ 3

// ---------------- scratch (device globals, POD only) ------------------------
__device__ unsigned short g_adj2 [(size_t)D_ * B_ * N_ * 2 * N_];   // 96 MB
__device__ unsigned short g_x2   [(size_t)B_ * N_ * 2 * F_];
__device__ unsigned short g_sup2 [(size_t)D_ * B_ * 2 * N_ * O_];
__device__ unsigned short g_agg2 [(size_t)D_ * B_ * N_ * 2 * O_];
__device__ unsigned short g_W2   [(size_t)L_ * D_ * 2 * F_ * O_];
__device__ unsigned short g_whhT2[(size_t)L_ * 2 * O_ * 3 * O_];
__device__ unsigned short g_wihT2[(size_t)L_ * 2 * O_ * 3 * O_];
__device__ unsigned short g_wh2  [(size_t)L_ * 2 * F_ * O_];
__device__ float g_gi  [(size_t)D_ * B_ * N_ * 3 * O_];
__device__ float g_gh  [(size_t)B_ * N_ * 3 * O_];
__device__ float g_thw [(size_t)B_ * N_ * O_];
__device__ float g_x   [(size_t)N_ * B_ * O_];
__device__ float g_whhT[(size_t)L_ * O_ * 3 * O_];
__device__ float g_wihT[(size_t)L_ * O_ * 3 * O_];

// ---------------- weight transpose: Wih/Whh [L,3O,O] -> [L,O,3O] -----------
__global__ void transpose_wts_kernel(const float* __restrict__ Wih,
                                     const float* __restrict__ Whh,
                                     float* __restrict__ WihT,
                                     float* __restrict__ WhhT) {
    int idx = blockIdx.x * blockDim.x + threadIdx.x;
    const int total = L_ * 3 * O_ * O_;
    if (idx >= total) return;
    int l = idx / (3 * O_ * O_);
    int r = idx % (3 * O_ * O_);
    int j = r / O_;
    int k = r % O_;
    int dst = l * O_ * 3 * O_ + k * 3 * O_ + j;
    WihT[dst] = Wih[idx];
    WhhT[dst] = Whh[idx];
}

// ---------------- hi/lo split helpers ---------------------------------------
__device__ __forceinline__ void split2(float a, float b, uint32_t& hi, uint32_t& lo) {
    __nv_bfloat162 h2 = __floats2bfloat162_rn(a, b);
    hi = *reinterpret_cast<const uint32_t*>(&h2);
    __nv_bfloat162 l2 = __floats2bfloat162_rn(a - __low2float(h2), b - __high2float(h2));
    lo = *reinterpret_cast<const uint32_t*>(&l2);
}

__device__ __forceinline__ void split_pack8(const float* v, uint32_t* ph, uint32_t* pl) {
#pragma unroll
    for (int i = 0; i < 4; i++) split2(v[2 * i], v[2 * i + 1], ph[i], pl[i]);
}

// splitA: fp32 (strided) [z][M][K] -> bf16 out[z][M][2K] = [hi | lo]
__global__ void splitA_kernel(const float* __restrict__ in,
                              unsigned short* __restrict__ out,
                              long inBatch, long inRow, int M, int K) {
    long idx = (long)blockIdx.x * blockDim.x + threadIdx.x;
    long total = (long)M * (K / 8);
    if (idx >= total) return;
    int m = (int)(idx / (K / 8));
    int kc = (int)(idx % (K / 8)) * 8;
    const float* src = in + (long)blockIdx.z * inBatch + (long)m * inRow + kc;
    float4 v0 = *(const float4*)(src);
    float4 v1 = *(const float4*)(src + 4);
    float v[8] = {v0.x, v0.y, v0.z, v0.w, v1.x, v1.y, v1.z, v1.w};
    uint32_t ph[4], pl[4];
    split_pack8(v, ph, pl);
    unsigned short* dst = out + (long)blockIdx.z * M * 2 * K + (long)m * 2 * K + kc;
    *(uint4*)(dst)     = make_uint4(ph[0], ph[1], ph[2], ph[3]);
    *(uint4*)(dst + K) = make_uint4(pl[0], pl[1], pl[2], pl[3]);
}

// splitB: fp32 contiguous [z][K][N] -> bf16 out[z][2K][N] = [hi ; lo]
__global__ void splitB_kernel(const float* __restrict__ in,
                              unsigned short* __restrict__ out,
                              int K, int Ncols) {
    long idx = (long)blockIdx.x * blockDim.x + threadIdx.x;
    long total = (long)K * (Ncols / 8);
    if (idx >= total) return;
    int k = (int)(idx / (Ncols / 8));
    int nc = (int)(idx % (Ncols / 8)) * 8;
    const float* src = in + (long)blockIdx.z * K * Ncols + (long)k * Ncols + nc;
    float4 v0 = *(const float4*)(src);
    float4 v1 = *(const float4*)(src + 4);
    float v[8] = {v0.x, v0.y, v0.z, v0.w, v1.x, v1.y, v1.z, v1.w};
    uint32_t ph[4], pl[4];
    split_pack8(v, ph, pl);
    unsigned short* dst = out + (long)blockIdx.z * 2 * K * Ncols + (long)k * Ncols + nc;
    *(uint4*)(dst)                   = make_uint4(ph[0], ph[1], ph[2], ph[3]);
    *(uint4*)(dst + (long)K * Ncols) = make_uint4(pl[0], pl[1], pl[2], pl[3]);
}

// ---------------- tensor-core GEMM primitives --------------------------------
__device__ __forceinline__ void ldsm_x4(uint32_t* r, uint32_t addr) {
    asm volatile("ldmatrix.sync.aligned.m8n8.x4.shared.b16 {%0,%1,%2,%3}, [%4];"
                 : "=r"(r[0]), "=r"(r[1]), "=r"(r[2]), "=r"(r[3]) : "r"(addr));
}
__device__ __forceinline__ void ldsm_x2t(uint32_t* r, uint32_t addr) {
    asm volatile("ldmatrix.sync.aligned.m8n8.x2.trans.shared.b16 {%0,%1}, [%2];"
                 : "=r"(r[0]), "=r"(r[1]) : "r"(addr));
}
__device__ __forceinline__ void mma_bf16(float* d, const uint32_t* a, const uint32_t* b) {
    asm volatile("mma.sync.aligned.m16n8k16.row.col.f32.bf16.bf16.f32 "
                 "{%0,%1,%2,%3}, {%4,%5,%6,%7}, {%8,%9}, {%0,%1,%2,%3};"
                 : "+f"(d[0]), "+f"(d[1]), "+f"(d[2]), "+f"(d[3])
                 : "r"(a[0]), "r"(a[1]), "r"(a[2]), "r"(a[3]), "r"(b[0]), "r"(b[1]));
}
__device__ __forceinline__ void cp16(uint32_t smem, const void* gptr) {
    asm volatile("cp.async.cg.shared.global [%0], [%1], 16;" :: "r"(smem), "l"(gptr));
}
__device__ __forceinline__ void cp_commit() {
    asm volatile("cp.async.commit_group;");
}
__device__ __forceinline__ void cp_wait2() {
    asm volatile("cp.async.wait_group 2;");
}

// C[z][m][n] = sum_{k3<3K} A2[m][aOff(k3)] * B2[bOff(k3)][n] (+ bias[n])
// A2: [M][2K]=[Ah|Al], B2: [2K][N]=[Bh;Bl]; terms Ah*Bh, Al*Bh, Ah*Bl.
// Tile 128x128x32, 8 warps (2x4), warp 64x32, cp.async 4-stage pipeline.
// emode: 0 = fp32 out; 1 = bf16 hi/lo B-layout (lo rows at +M); 2 = bf16 hi/lo
//        A-layout (row width 2*Ncols, lo cols at +Ncols).
__global__ __launch_bounds__(256, 2)
void gemm_bf16_kernel(const unsigned short* __restrict__ A2,
                      const unsigned short* __restrict__ B2,
                      void* __restrict__ Cout, const float* __restrict__ bias,
                      int M, int K, int Ncols,
                      long sAd, long sAb, long sBd, long sBb,
                      long sCb, long sBiasD, int BB, int emode) {
    const int z = blockIdx.z;
    const int d = z / BB;
    const int b = z % BB;
    A2 += (long)d * sAd + (long)b * sAb;
    B2 += (long)d * sBd + (long)b * sBb;

    const int twoK = 2 * K;
    const int row0 = blockIdx.y * 128;
    const int col0 = blockIdx.x * 128;

    __shared__ uint4 As4[4][512];
    __shared__ uint4 Bs4[4][512];

    const int tid  = threadIdx.x;
    const int lane = tid & 31;
    const int warp = tid >> 5;
    const int wm = warp >> 2;
    const int wn = warp & 3;

    const int arow0 = tid >> 2, ac = tid & 3;
    const int brow0 = tid >> 4, bc = tid & 15;

    const unsigned short* Ag0 = A2 + (long)(row0 + arow0) * twoK + ac * 8;
    const unsigned short* Ag1 = A2 + (long)(row0 + arow0 + 64) * twoK + ac * 8;
    const unsigned short* Bg0 = B2 + (long)brow0 * Ncols + col0 + bc * 8;
    const unsigned short* Bg1 = B2 + (long)(brow0 + 16) * Ncols + col0 + bc * 8;

    const int asIdx0 = arow0 * 4 + (ac ^ ((arow0 >> 1) & 3));
    const int asIdx1 = asIdx0 + 256;
    const int bsIdx0 = brow0 * 16 + (bc ^ (brow0 & 7));
    const int bsIdx1 = bsIdx0 + 256;

    const uint32_t asB = (uint32_t)__cvta_generic_to_shared(&As4[0][0]);
    const uint32_t bsB = (uint32_t)__cvta_generic_to_shared(&Bs4[0][0]);

    // per-thread staging smem byte addresses (stage 0)
    const uint32_t stA0 = asB + (uint32_t)asIdx0 * 16u;
    const uint32_t stA1 = asB + (uint32_t)asIdx1 * 16u;
    const uint32_t stB0 = bsB + (uint32_t)bsIdx0 * 16u;
    const uint32_t stB1 = bsB + (uint32_t)bsIdx1 * 16u;

    uint32_t aAddr[2][4], bAddr[2][4];
#pragma unroll
    for (int ks = 0; ks < 2; ks++) {
#pragma unroll
        for (int mi = 0; mi < 4; mi++) {
            int r = wm * 64 + mi * 16 + (lane & 15);
            int c = ks * 2 + (lane >> 4);
            aAddr[ks][mi] = asB + (uint32_t)(r * 4 + (c ^ ((r >> 1) & 3))) * 16u;
        }
#pragma unroll
        for (int ni = 0; ni < 4; ni++) {
            int r = ks * 16 + (lane & 15);
            int c = wn * 4 + ni;
            bAddr[ks][ni] = bsB + (uint32_t)(r * 16 + (c ^ (r & 7))) * 16u;
        }
    }

    float acc[4][4][4];
#pragma unroll
    for (int mi = 0; mi < 4; mi++)
#pragma unroll
        for (int ni = 0; ni < 4; ni++)
#pragma unroll
            for (int q = 0; q < 4; q++) acc[mi][ni][q] = 0.f;

    const int nT = (3 * K) >> 5;

    // issue one stage's loads into buffer `stg`
    auto issue = [&](int kt, int stg) {
        const int k3 = kt << 5;
        const int aOff = k3 - (k3 >= twoK ? twoK : 0);
        const int bOff = k3 - (k3 >= K ? K : 0);
        const uint32_t so = (uint32_t)stg * 8192u;
        cp16(stA0 + so, Ag0 + aOff);
        cp16(stA1 + so, Ag1 + aOff);
        cp16(stB0 + so, Bg0 + (long)bOff * Ncols);
        cp16(stB1 + so, Bg1 + (long)bOff * Ncols);
    };

    issue(0, 0); cp_commit();
    issue(1, 1); cp_commit();

    for (int kt = 0; kt < nT; kt++) {
        if (kt + 2 < nT) issue(kt + 2, (kt + 2) & 3);
        cp_commit();
        cp_wait2();
        __syncthreads();

        const uint32_t bofs = (uint32_t)(kt & 3) * 8192u;
#pragma unroll
        for (int ks = 0; ks < 2; ks++) {
            uint32_t afr[4][4], bfr[4][2];
#pragma unroll
            for (int mi = 0; mi < 4; mi++) ldsm_x4(afr[mi], aAddr[ks][mi] + bofs);
#pragma unroll
            for (int ni = 0; ni < 4; ni++) ldsm_x2t(bfr[ni], bAddr[ks][ni] + bofs);
#pragma unroll
            for (int mi = 0; mi < 4; mi++)
#pragma unroll
                for (int ni = 0; ni < 4; ni++)
                    mma_bf16(acc[mi][ni], afr[mi], bfr[ni]);
        }
    }

    const float* bp = bias ? (bias + (long)d * sBiasD) : (const float*)0;
    float* Cf = (float*)Cout + (long)z * sCb;
    unsigned short* Cb = (unsigned short*)Cout + (long)z * sCb;

#pragma unroll
    for (int mi = 0; mi < 4; mi++) {
        const int r0 = row0 + wm * 64 + mi * 16 + (lane >> 2);
        const int r1 = r0 + 8;
#pragma unroll
        for (int ni = 0; ni < 4; ni++) {
            const int cc = col0 + wn * 32 + ni * 8 + (lane & 3) * 2;
            float bx = 0.f, by = 0.f;
            if (bp) { bx = bp[cc]; by = bp[cc + 1]; }
            const float v00 = acc[mi][ni][0] + bx;
            const float v01 = acc[mi][ni][1] + by;
            const float v10 = acc[mi][ni][2] + bx;
            const float v11 = acc[mi][ni][3] + by;
            if (emode == 0) {
                float* p0 = Cf + (long)r0 * Ncols + cc;
                float* p1 = Cf + (long)r1 * Ncols + cc;
                p0[0] = v00; p0[1] = v01;
                p1[0] = v10; p1[1] = v11;
            } else if (emode == 1) {
                uint32_t h0, l0, h1, l1;
                split2(v00, v01, h0, l0);
                split2(v10, v11, h1, l1);
                *(uint32_t*)(Cb + (long)r0 * Ncols + cc)       = h0;
                *(uint32_t*)(Cb + (long)(M + r0) * Ncols + cc) = l0;
                *(uint32_t*)(Cb + (long)r1 * Ncols + cc)       = h1;
                *(uint32_t*)(Cb + (long)(M + r1) * Ncols + cc) = l1;
            } else {
                const long rs = 2L * Ncols;
                uint32_t h0, l0, h1, l1;
                split2(v00, v01, h0, l0);
                split2(v10, v11, h1, l1);
                *(uint32_t*)(Cb + (long)r0 * rs + cc)         = h0;
                *(uint32_t*)(Cb + (long)r0 * rs + Ncols + cc) = l0;
                *(uint32_t*)(Cb + (long)r1 * rs + cc)         = h1;
                *(uint32_t*)(Cb + (long)r1 * rs + Ncols + cc) = l1;
            }
        }
    }
}

// ---------------- fused GRU + d-sum + relu + highway (+ next-layer split) --
__device__ __forceinline__ float sigm(float x) { return 1.f / (1.f + expf(-x)); }

__global__ void gru_combine_kernel(const float* __restrict__ gi,
                                   const float* __restrict__ gh,
                                   const float* __restrict__ xsrc,
                                   const float* __restrict__ thw,
                                   float* __restrict__ xdst,
                                   unsigned short* __restrict__ x2out) {
    int idx = blockIdx.x * blockDim.x + threadIdx.x;  // (n,b,o)
    if (idx >= N_ * B_ * O_) return;
    const int o = idx & (O_ - 1);
    const int nb = idx / O_;
    const int b = nb & (B_ - 1);
    const int n = nb / B_;

    const float h = xsrc[idx];
    const long ghbase = ((long)b * N_ + n) * (3 * O_);
    const float ghr = gh[ghbase + o];
    const float ghz = gh[ghbase + O_ + o];
    const float ghn = gh[ghbase + 2 * O_ + o];

    float acc = 0.f;
#pragma unroll
    for (int d = 0; d < D_; d++) {
        const long gbase = (((long)d * B_ + b) * N_ + n) * (3 * O_);
        const float gir = gi[gbase + o];
        const float giz = gi[gbase + O_ + o];
        const float gin = gi[gbase + 2 * O_ + o];
        const float r = sigm(gir + ghr);
        const float zz = sigm(giz + ghz);
        const float nn = tanhf(gin + r * ghn);
        acc += (1.f - zz) * nn + zz * h;
    }
    const float outv = fmaxf(acc, 0.f);
    const float t = fmaxf(thw[((long)b * N_ + n) * O_ + o], 0.f);
    const float val = outv * t + h * (1.f - t);
    xdst[idx] = val;
    if (x2out) {
        __nv_bfloat16 hi = __float2bfloat16_rn(val);
        __nv_bfloat16 lo = __float2bfloat16_rn(val - __bfloat162float(hi));
        const long base = ((long)b * N_ + n) * (2 * F_) + o;
        x2out[base]      = *reinterpret_cast<const unsigned short*>(&hi);
        x2out[base + F_] = *reinterpret_cast<const unsigned short*>(&lo);
    }
}

// ---------------- launch ----------------------------------------------------
extern "C" void kernel_launch(void* const* d_in, const int* in_sizes, int n_in,
                              void* d_out, int out_size) {
    const float* inputs = (const float*)d_in[0];
    const float* adj    = (const float*)d_in[1];
    const float* W      = (const float*)d_in[2];
    const float* Bc     = (const float*)d_in[3];
    const float* Wh     = (const float*)d_in[4];
    const float* Bh     = (const float*)d_in[5];
    const float* Wih    = (const float*)d_in[6];
    const float* Whh    = (const float*)d_in[7];
    const float* bih    = (const float*)d_in[8];
    const float* bhh    = (const float*)d_in[9];
    float* out = (float*)d_out;

    unsigned short *adj2, *x2, *sup2, *agg2, *W2, *whhT2, *wihT2, *wh2;
    float *gi, *gh, *thw, *xbuf, *whhT, *wihT;
    cudaGetSymbolAddress((void**)&adj2,  g_adj2);
    cudaGetSymbolAddress((void**)&x2,    g_x2);
    cudaGetSymbolAddress((void**)&sup2,  g_sup2);
    cudaGetSymbolAddress((void**)&agg2,  g_agg2);
    cudaGetSymbolAddress((void**)&W2,    g_W2);
    cudaGetSymbolAddress((void**)&whhT2, g_whhT2);
    cudaGetSymbolAddress((void**)&wihT2, g_wihT2);
    cudaGetSymbolAddress((void**)&wh2,   g_wh2);
    cudaGetSymbolAddress((void**)&gi,    g_gi);
    cudaGetSymbolAddress((void**)&gh,    g_gh);
    cudaGetSymbolAddress((void**)&thw,   g_thw);
    cudaGetSymbolAddress((void**)&xbuf,  g_x);
    cudaGetSymbolAddress((void**)&whhT,  g_whhT);
    cudaGetSymbolAddress((void**)&wihT,  g_wihT);

    // ---- one-time conversions ----
    transpose_wts_kernel<<<(L_ * 3 * O_ * O_ + 255) / 256, 256>>>(Wih, Whh, wihT, whhT);
    splitB_kernel<<<dim3((F_ * O_ / 8 + 255) / 256, 1, L_ * D_), 256>>>(W, W2, F_, O_);
    splitB_kernel<<<dim3((O_ * 3 * O_ / 8 + 255) / 256, 1, L_), 256>>>(whhT, whhT2, O_, 3 * O_);
    splitB_kernel<<<dim3((O_ * 3 * O_ / 8 + 255) / 256, 1, L_), 256>>>(wihT, wihT2, O_, 3 * O_);
    splitB_kernel<<<dim3((F_ * O_ / 8 + 255) / 256, 1, L_), 256>>>(Wh, wh2, F_, O_);
    splitA_kernel<<<dim3((N_ * N_ / 8 + 255) / 256, 1, D_ * B_), 256>>>(
        adj, adj2, (long)N_ * N_, (long)N_, N_, N_);
    // x2 for layer 0 from inputs [N,B,F]
    splitA_kernel<<<dim3((N_ * F_ / 8 + 255) / 256, 1, B_), 256>>>(
        inputs, x2, (long)F_, (long)B_ * F_, N_, F_);

    for (int l = 0; l < L_; l++) {
        const float* xs = (l == 0) ? inputs : xbuf;
        float* xd = (l == L_ - 1) ? out : xbuf;

        // sup2[d,b] (bf16 B-layout) = split( x2[b] @ W2[l,d] + Bc[l,d] )
        gemm_bf16_kernel<<<dim3(1, N_ / 128, D_ * B_), 256>>>(
            x2, W2 + (long)l * D_ * 2 * F_ * O_, sup2, Bc + (long)l * D_ * O_,
            N_, F_, O_,
            0, (long)N_ * 2 * F_, (long)2 * F_ * O_, 0,
            (long)2 * N_ * O_, O_, B_, 1);

        // agg2[d,b] (bf16 A-layout) = split( adj2[d,b] @ sup2[d,b] )
        gemm_bf16_kernel<<<dim3(1, N_ / 128, D_ * B_), 256>>>(
            adj2, sup2, agg2, (const float*)0,
            N_, N_, O_,
            (long)B_ * N_ * 2 * N_, (long)N_ * 2 * N_,
            (long)B_ * 2 * N_ * O_, (long)2 * N_ * O_,
            (long)N_ * 2 * O_, 0, B_, 2);

        // gh[b] = x2[b] @ whhT2[l] + bhh[l]
        gemm_bf16_kernel<<<dim3(3, N_ / 128, B_), 256>>>(
            x2, whhT2 + (long)l * 2 * O_ * 3 * O_, gh, bhh + (long)l * 3 * O_,
            N_, O_, 3 * O_,
            0, (long)N_ * 2 * F_, 0, 0,
            (long)N_ * 3 * O_, 0, B_, 0);

        // gi[d,b] = agg2[d,b] @ wihT2[l] + bih[l]
        gemm_bf16_kernel<<<dim3(3, N_ / 128, D_ * B_), 256>>>(
            agg2, wihT2 + (long)l * 2 * O_ * 3 * O_, gi, bih + (long)l * 3 * O_,
            N_, O_, 3 * O_,
            (long)B_ * N_ * 2 * O_, (long)N_ * 2 * O_, 0, 0,
            (long)N_ * 3 * O_, 0, B_, 0);

        // thw[b] = x2[b] @ wh2[l] + Bh[l]
        gemm_bf16_kernel<<<dim3(1, N_ / 128, B_), 256>>>(
            x2, wh2 + (long)l * 2 * F_ * O_, thw, Bh + (long)l * O_,
            N_, F_, O_,
            0, (long)N_ * 2 * F_, 0, 0,
            (long)N_ * O_, 0, B_, 0);

        gru_combine_kernel<<<(N_ * B_ * O_) / 256, 256>>>(
            gi, gh, xs, thw, xd, (l < L_ - 1) ? x2 : (unsigned short*)0);
    }
}